// round 1
// baseline (speedup 1.0000x reference)
#include <cuda_runtime.h>
#include <cuda_bf16.h>
#include <math.h>

#define TT 1024   // time steps
#define NB 256    // sequences (blocks)
#define DX 16
#define DU 16
#define DA 32
#define NT 256    // threads per block
#define CH 128    // phase-B chunk length
#define CONV_EPS 1e-7f

__global__ __launch_bounds__(NT, 1)
void ldm_forward_kernel(const float* __restrict__ a_g,
                        const float* __restrict__ u_g,
                        const float* __restrict__ mask_g,
                        const float* __restrict__ A_g,
                        const float* __restrict__ B_g,
                        const float* __restrict__ C_g,
                        const float* __restrict__ mu0_g,
                        const float* __restrict__ Lam0_g,
                        const float* __restrict__ Wl_g,
                        const float* __restrict__ Rl_g,
                        float* __restrict__ out)
{
    const int b   = blockIdx.x;
    const int tid = threadIdx.x;

    float* mu_pred_out = out;                                   // [T][B][DX]
    float* mu_t_out    = out + (size_t)TT * NB * DX;            // [T][B][DX]
    float* Lp_out      = out + (size_t)2 * TT * NB * DX;        // [T][B][DX*DX]
    float* Lt_out      = Lp_out + (size_t)TT * NB * DX * DX;    // [T][B][DX*DX]

    __shared__ float Cs[DA][DX + 1];
    __shared__ float As[DX][DX + 1];
    __shared__ float Bs[DX][DU + 1];
    __shared__ float Wd[DX];
    __shared__ float Rd[DA];
    __shared__ float P[DX][DX + 1];       // Lambda_pred (current)
    __shared__ float PCt[DX][DA + 1];
    __shared__ float S[DA][DA + 1];       // S -> Sinv in place
    __shared__ float Kk[DX][DA + 1];      // masked Kalman gain
    __shared__ float KC[DX][DX + 1];
    __shared__ float Lt[DX][DX + 1];      // Lambda_t
    __shared__ float AL[DX][DX + 1];
    __shared__ float Pn[DX][DX + 1];      // Lambda_pred next
    __shared__ float Fm[DX][DX + 1];      // I - K C (frozen)
    __shared__ float Mm[DX][DX + 1];      // A (I - K C) (frozen)
    __shared__ float colk[DA];
    __shared__ float sa[DA];
    __shared__ float su[DU];
    __shared__ float mu[2][DX];
    __shared__ float mut[DX];
    __shared__ float rr[DA];
    __shared__ float gbuf[CH][DX + 1];
    __shared__ float hbuf[CH][DX + 1];
    __shared__ float wmax[NT / 32];
    __shared__ float smv;
    __shared__ int   lastChange;
    __shared__ int   convFlag;

    // ---------------- init constants ----------------
    for (int i = tid; i < DA * DX; i += NT) Cs[i / DX][i % DX] = C_g[i];
    for (int i = tid; i < DX * DX; i += NT) {
        As[i / DX][i % DX] = A_g[i];
        P[i / DX][i % DX]  = Lam0_g[i];
    }
    for (int i = tid; i < DX * DU; i += NT) Bs[i / DU][i % DU] = B_g[i];
    if (tid < DX) { Wd[tid] = expf(Wl_g[tid]); mu[0][tid] = mu0_g[tid]; }
    if (tid < DA) Rd[tid] = expf(Rl_g[tid]);
    if (tid == 0) { lastChange = 0; convFlag = 0; }
    __syncthreads();

    // last time index where the mask changes (freeze only allowed after it)
    {
        int lc = 0;
        for (int t = tid + 1; t < TT; t += NT) {
            if (mask_g[(size_t)b * TT + t] != mask_g[(size_t)b * TT + t - 1]) lc = t;
        }
        atomicMax(&lastChange, lc);
    }
    __syncthreads();

    const int x16 = tid >> 4;       // 16x16 element map
    const int y16 = tid & 15;

    int mup   = 0;     // mu double-buffer parity
    int tconv = TT;    // first phase-B step

    // ================ Phase A: exact Kalman steps ================
    for (int t = 0; t < TT; ++t) {
        if (tid < DA) sa[tid] = a_g[((size_t)b * TT + t) * DA + tid];
        if (tid < DU) su[tid] = (t == TT - 1) ? 0.f
                               : u_g[((size_t)b * TT + t) * DU + tid];
        if (tid == 0) smv = mask_g[(size_t)b * TT + t];
        __syncthreads();
        const float m = smv;

        // PCt[x][a] = sum_y P[x][y] * C[a][y]
        #pragma unroll
        for (int q = 0; q < 2; ++q) {
            int e = tid + q * NT, x = e >> 5, aa = e & 31;
            float s = 0.f;
            #pragma unroll
            for (int y = 0; y < DX; ++y) s += P[x][y] * Cs[aa][y];
            PCt[x][aa] = s;
        }
        // residual r = m*a - C mu_pred  (independent of PCt)
        if (tid < DA) {
            float s = 0.f;
            #pragma unroll
            for (int y = 0; y < DX; ++y) s += Cs[tid][y] * mu[mup][y];
            rr[tid] = m * sa[tid] - s;
        }
        __syncthreads();

        // S[i][j] = sum_x C[i][x] * PCt[x][j] + diag(R)
        #pragma unroll
        for (int q = 0; q < 4; ++q) {
            int e = tid + q * NT, i = e >> 5, j = e & 31;
            float s = (i == j) ? Rd[i] : 0.f;
            #pragma unroll
            for (int x = 0; x < DX; ++x) s += Cs[i][x] * PCt[x][j];
            S[i][j] = s;
        }
        __syncthreads();

        // in-place Gauss-Jordan inverse (no pivoting; S is SPD)
        for (int k = 0; k < DA; ++k) {
            float d = __frcp_rn(S[k][k]);
            if (tid < DA) {
                colk[tid] = S[tid][k];
            } else if (tid < 2 * DA) {
                int j = tid - DA;
                if (j != k) S[k][j] *= d;
            }
            __syncthreads();
            #pragma unroll
            for (int q = 0; q < 4; ++q) {
                int e = tid + q * NT, i = e >> 5, j = e & 31;
                if (i == k) {
                    if (j == k) S[k][k] = d;
                } else if (j == k) {
                    S[i][k] = -colk[i] * d;
                } else {
                    S[i][j] -= colk[i] * S[k][j];
                }
            }
            __syncthreads();
        }

        // K = m * PCt * Sinv
        #pragma unroll
        for (int q = 0; q < 2; ++q) {
            int e = tid + q * NT, x = e >> 5, aa = e & 31;
            float s = 0.f;
            #pragma unroll
            for (int j = 0; j < DA; ++j) s += PCt[x][j] * S[j][aa];
            Kk[x][aa] = m * s;
        }
        __syncthreads();

        // KC = K*C ; mu_t = mu_pred + K r
        {
            float s = 0.f;
            #pragma unroll
            for (int aa = 0; aa < DA; ++aa) s += Kk[x16][aa] * Cs[aa][y16];
            KC[x16][y16] = s;
        }
        if (tid < DX) {
            float s = mu[mup][tid];
            #pragma unroll
            for (int aa = 0; aa < DA; ++aa) s += Kk[tid][aa] * rr[aa];
            mut[tid] = s;
        }
        __syncthreads();

        // Lam_t = (I - KC) P ; mu_pred' = A mu_t + B u_t
        {
            float s = P[x16][y16];
            #pragma unroll
            for (int z = 0; z < DX; ++z) s -= KC[x16][z] * P[z][y16];
            Lt[x16][y16] = s;
        }
        if (tid < DX) {
            float s = 0.f;
            #pragma unroll
            for (int y = 0; y < DX; ++y) s += As[tid][y] * mut[y];
            #pragma unroll
            for (int uu = 0; uu < DU; ++uu) s += Bs[tid][uu] * su[uu];
            mu[1 - mup][tid] = s;
        }
        __syncthreads();

        // AL = A * Lam_t
        {
            float s = 0.f;
            #pragma unroll
            for (int z = 0; z < DX; ++z) s += As[x16][z] * Lt[z][y16];
            AL[x16][y16] = s;
        }
        __syncthreads();

        // Pn = AL * A^T + W ; convergence diff
        float mydiff;
        {
            float s = (x16 == y16) ? Wd[x16] : 0.f;
            #pragma unroll
            for (int z = 0; z < DX; ++z) s += AL[x16][z] * As[y16][z];
            Pn[x16][y16] = s;
            mydiff = fabsf(s - P[x16][y16]);
        }
        #pragma unroll
        for (int o = 16; o; o >>= 1)
            mydiff = fmaxf(mydiff, __shfl_xor_sync(0xffffffffu, mydiff, o));
        if ((tid & 31) == 0) wmax[tid >> 5] = mydiff;
        __syncthreads();

        // write outputs for step t; advance state
        {
            size_t ob = (size_t)t * NB + b;
            Lp_out[ob * 256 + tid] = Pn[x16][y16];
            Lt_out[ob * 256 + tid] = Lt[x16][y16];
            if (tid < DX) {
                mu_pred_out[ob * DX + tid] = mu[1 - mup][tid];
                mu_t_out[ob * DX + tid]    = mut[tid];
            }
            P[x16][y16] = Pn[x16][y16];
        }
        if (tid == 0) {
            float md = wmax[0];
            #pragma unroll
            for (int w = 1; w < NT / 32; ++w) md = fmaxf(md, wmax[w]);
            convFlag = (md < CONV_EPS && t >= lastChange && t < TT - 1) ? 1 : 0;
        }
        mup = 1 - mup;
        __syncthreads();
        if (convFlag) { tconv = t + 1; break; }
    }

    // ================ Phase B: frozen-gain fast path ================
    if (tconv < TT) {
        // Fm = I - KC ; Mm = A * Fm
        Fm[x16][y16] = ((x16 == y16) ? 1.f : 0.f) - KC[x16][y16];
        __syncthreads();
        {
            float s = 0.f;
            #pragma unroll
            for (int z = 0; z < DX; ++z) s += As[x16][z] * Fm[z][y16];
            Mm[x16][y16] = s;
        }
        __syncthreads();

        const float pn_v = Pn[x16][y16];   // frozen Lambda_pred
        const float lt_v = Lt[x16][y16];   // frozen Lambda_t

        float fr[DX], mr[DX];
        if (tid < DX) {
            #pragma unroll
            for (int j = 0; j < DX; ++j) { fr[j] = Fm[tid][j]; mr[j] = Mm[tid][j]; }
        }

        for (int t0 = tconv; t0 < TT; t0 += CH) {
            const int L = min(CH, TT - t0);

            // g_t = K * (m_t * a_t)
            for (int e = tid; e < L * DX; e += NT) {
                int s = e >> 4, x = e & 15;
                int t = t0 + s;
                float mv = mask_g[(size_t)b * TT + t];
                const float* ap = a_g + ((size_t)b * TT + t) * DA;
                float g = 0.f;
                #pragma unroll
                for (int aa = 0; aa < DA; ++aa) g += Kk[x][aa] * ap[aa];
                gbuf[s][x] = mv * g;
            }
            __syncthreads();

            // h_t = A*g_t + B*u_t  (u = 0 at final step)
            for (int e = tid; e < L * DX; e += NT) {
                int s = e >> 4, x = e & 15;
                int t = t0 + s;
                float h = 0.f;
                #pragma unroll
                for (int z = 0; z < DX; ++z) h += As[x][z] * gbuf[s][z];
                if (t != TT - 1) {
                    const float* up = u_g + ((size_t)b * TT + t) * DU;
                    #pragma unroll
                    for (int uu = 0; uu < DU; ++uu) h += Bs[x][uu] * up[uu];
                }
                hbuf[s][x] = h;
            }
            __syncthreads();

            // serial 16-dim recurrence + frozen-Lambda fill
            for (int s = 0; s < L; ++s) {
                size_t ob = (size_t)(t0 + s) * NB + b;
                if (tid < DX) {
                    float mt = gbuf[s][tid];
                    float mn = hbuf[s][tid];
                    #pragma unroll
                    for (int j = 0; j < DX; ++j) {
                        float mj = mu[mup][j];
                        mt += fr[j] * mj;
                        mn += mr[j] * mj;
                    }
                    mu_t_out[ob * DX + tid]    = mt;
                    mu_pred_out[ob * DX + tid] = mn;
                    mu[1 - mup][tid] = mn;
                }
                Lp_out[ob * 256 + tid] = pn_v;
                Lt_out[ob * 256 + tid] = lt_v;
                mup ^= 1;
                __syncthreads();
            }
        }
    }
}

extern "C" void kernel_launch(void* const* d_in, const int* in_sizes, int n_in,
                              void* d_out, int out_size)
{
    (void)in_sizes; (void)n_in; (void)out_size;
    ldm_forward_kernel<<<NB, NT>>>(
        (const float*)d_in[0],   // a
        (const float*)d_in[1],   // u
        (const float*)d_in[2],   // mask
        (const float*)d_in[3],   // A
        (const float*)d_in[4],   // B
        (const float*)d_in[5],   // C
        (const float*)d_in[6],   // mu_0
        (const float*)d_in[7],   // Lambda_0
        (const float*)d_in[8],   // W_log_diag
        (const float*)d_in[9],   // R_log_diag
        (float*)d_out);
}

// round 2
// speedup vs baseline: 1.8654x; 1.8654x over previous
#include <cuda_runtime.h>
#include <cuda_bf16.h>
#include <math.h>

#define TT 1024   // time steps
#define NB 256    // sequences (blocks)
#define DX 16
#define DU 16
#define DA 32
#define NT 256    // threads per block
#define CH 64     // phase-B chunk length
#define CONV_EPS 1e-7f

__global__ __launch_bounds__(NT, 1)
void ldm_forward_kernel(const float* __restrict__ a_g,
                        const float* __restrict__ u_g,
                        const float* __restrict__ mask_g,
                        const float* __restrict__ A_g,
                        const float* __restrict__ B_g,
                        const float* __restrict__ C_g,
                        const float* __restrict__ mu0_g,
                        const float* __restrict__ Lam0_g,
                        const float* __restrict__ Wl_g,
                        const float* __restrict__ Rl_g,
                        float* __restrict__ out)
{
    const int b   = blockIdx.x;
    const int tid = threadIdx.x;

    float* mu_pred_out = out;                                   // [T][B][DX]
    float* mu_t_out    = out + (size_t)TT * NB * DX;            // [T][B][DX]
    float* Lp_out      = out + (size_t)2 * TT * NB * DX;        // [T][B][DX*DX]
    float* Lt_out      = Lp_out + (size_t)TT * NB * DX * DX;    // [T][B][DX*DX]

    __shared__ float Cs[DA][DX + 1];
    __shared__ float As[DX][DX + 1];
    __shared__ float Bs[DX][DU + 1];
    __shared__ float Wd[DX];
    __shared__ float Rd[DA];
    __shared__ float P[DX][DX + 1];       // Lambda_pred (current)
    __shared__ float PCt[DX][DA + 1];
    __shared__ float S[DA][DA + 1];       // S -> Sinv in place
    __shared__ float Kk[DX][DA + 1];      // masked Kalman gain
    __shared__ float KC[DX][DX + 1];
    __shared__ float Lt[DX][DX + 1];      // Lambda_t
    __shared__ float AL[DX][DX + 1];
    __shared__ float Pn[DX][DX + 1];      // Lambda_pred next
    __shared__ float Fm[DX][DX + 1];      // I - K C (frozen)
    __shared__ float Mm[DX][DX + 1];      // A (I - K C) (frozen)
    __shared__ float colk[DA];
    __shared__ float sa[DA];
    __shared__ float su[DU];
    __shared__ float mu[2][DX];
    __shared__ float mut[DX];
    __shared__ float rr[DA];
    __shared__ float wmax[NT / 32];
    __shared__ float smv;
    __shared__ int   lastChange;
    __shared__ int   convFlag;
    // Phase-B staging
    __shared__ __align__(16) float abuf[CH * DA];      // 8 KB
    __shared__ __align__(16) float ubuf[CH * DU];      // 4 KB
    __shared__ float mbuf[CH];
    __shared__ float gbuf[CH][DX + 1];                 // 4.4 KB
    __shared__ float hbuf[CH][DX + 1];                 // 4.4 KB
    __shared__ __align__(16) float LpTile[256];        // frozen Lambda_pred
    __shared__ __align__(16) float LtTile[256];        // frozen Lambda_t

    // ---------------- init constants ----------------
    for (int i = tid; i < DA * DX; i += NT) Cs[i / DX][i % DX] = C_g[i];
    for (int i = tid; i < DX * DX; i += NT) {
        As[i / DX][i % DX] = A_g[i];
        P[i / DX][i % DX]  = Lam0_g[i];
    }
    for (int i = tid; i < DX * DU; i += NT) Bs[i / DU][i % DU] = B_g[i];
    if (tid < DX) { Wd[tid] = expf(Wl_g[tid]); mu[0][tid] = mu0_g[tid]; }
    if (tid < DA) Rd[tid] = expf(Rl_g[tid]);
    if (tid == 0) { lastChange = 0; convFlag = 0; }
    __syncthreads();

    // last time index where the mask changes (freeze only allowed after it)
    {
        int lc = 0;
        for (int t = tid + 1; t < TT; t += NT) {
            if (mask_g[(size_t)b * TT + t] != mask_g[(size_t)b * TT + t - 1]) lc = t;
        }
        atomicMax(&lastChange, lc);
    }
    __syncthreads();

    const int x16 = tid >> 4;       // 16x16 element map
    const int y16 = tid & 15;

    int mup   = 0;     // mu double-buffer parity
    int tconv = TT;    // first phase-B step

    // ================ Phase A: exact Kalman steps ================
    for (int t = 0; t < TT; ++t) {
        if (tid < DA) sa[tid] = a_g[((size_t)b * TT + t) * DA + tid];
        if (tid < DU) su[tid] = (t == TT - 1) ? 0.f
                               : u_g[((size_t)b * TT + t) * DU + tid];
        if (tid == 0) smv = mask_g[(size_t)b * TT + t];
        __syncthreads();
        const float m = smv;

        // PCt[x][a] = sum_y P[x][y] * C[a][y]
        #pragma unroll
        for (int q = 0; q < 2; ++q) {
            int e = tid + q * NT, x = e >> 5, aa = e & 31;
            float s = 0.f;
            #pragma unroll
            for (int y = 0; y < DX; ++y) s += P[x][y] * Cs[aa][y];
            PCt[x][aa] = s;
        }
        // residual r = m*a - C mu_pred
        if (tid < DA) {
            float s = 0.f;
            #pragma unroll
            for (int y = 0; y < DX; ++y) s += Cs[tid][y] * mu[mup][y];
            rr[tid] = m * sa[tid] - s;
        }
        __syncthreads();

        // S[i][j] = sum_x C[i][x] * PCt[x][j] + diag(R)
        #pragma unroll
        for (int q = 0; q < 4; ++q) {
            int e = tid + q * NT, i = e >> 5, j = e & 31;
            float s = (i == j) ? Rd[i] : 0.f;
            #pragma unroll
            for (int x = 0; x < DX; ++x) s += Cs[i][x] * PCt[x][j];
            S[i][j] = s;
        }
        __syncthreads();

        // in-place Gauss-Jordan inverse (no pivoting; S is SPD)
        for (int k = 0; k < DA; ++k) {
            float d = __frcp_rn(S[k][k]);
            if (tid < DA) {
                colk[tid] = S[tid][k];
            } else if (tid < 2 * DA) {
                int j = tid - DA;
                if (j != k) S[k][j] *= d;
            }
            __syncthreads();
            #pragma unroll
            for (int q = 0; q < 4; ++q) {
                int e = tid + q * NT, i = e >> 5, j = e & 31;
                if (i == k) {
                    if (j == k) S[k][k] = d;
                } else if (j == k) {
                    S[i][k] = -colk[i] * d;
                } else {
                    S[i][j] -= colk[i] * S[k][j];
                }
            }
            __syncthreads();
        }

        // K = m * PCt * Sinv
        #pragma unroll
        for (int q = 0; q < 2; ++q) {
            int e = tid + q * NT, x = e >> 5, aa = e & 31;
            float s = 0.f;
            #pragma unroll
            for (int j = 0; j < DA; ++j) s += PCt[x][j] * S[j][aa];
            Kk[x][aa] = m * s;
        }
        __syncthreads();

        // KC = K*C ; mu_t = mu_pred + K r
        {
            float s = 0.f;
            #pragma unroll
            for (int aa = 0; aa < DA; ++aa) s += Kk[x16][aa] * Cs[aa][y16];
            KC[x16][y16] = s;
        }
        if (tid < DX) {
            float s = mu[mup][tid];
            #pragma unroll
            for (int aa = 0; aa < DA; ++aa) s += Kk[tid][aa] * rr[aa];
            mut[tid] = s;
        }
        __syncthreads();

        // Lam_t = (I - KC) P ; mu_pred' = A mu_t + B u_t
        {
            float s = P[x16][y16];
            #pragma unroll
            for (int z = 0; z < DX; ++z) s -= KC[x16][z] * P[z][y16];
            Lt[x16][y16] = s;
        }
        if (tid < DX) {
            float s = 0.f;
            #pragma unroll
            for (int y = 0; y < DX; ++y) s += As[tid][y] * mut[y];
            #pragma unroll
            for (int uu = 0; uu < DU; ++uu) s += Bs[tid][uu] * su[uu];
            mu[1 - mup][tid] = s;
        }
        __syncthreads();

        // AL = A * Lam_t
        {
            float s = 0.f;
            #pragma unroll
            for (int z = 0; z < DX; ++z) s += As[x16][z] * Lt[z][y16];
            AL[x16][y16] = s;
        }
        __syncthreads();

        // Pn = AL * A^T + W ; convergence diff
        float mydiff;
        {
            float s = (x16 == y16) ? Wd[x16] : 0.f;
            #pragma unroll
            for (int z = 0; z < DX; ++z) s += AL[x16][z] * As[y16][z];
            Pn[x16][y16] = s;
            mydiff = fabsf(s - P[x16][y16]);
        }
        #pragma unroll
        for (int o = 16; o; o >>= 1)
            mydiff = fmaxf(mydiff, __shfl_xor_sync(0xffffffffu, mydiff, o));
        if ((tid & 31) == 0) wmax[tid >> 5] = mydiff;
        __syncthreads();

        // write outputs for step t; advance state
        {
            size_t ob = (size_t)t * NB + b;
            Lp_out[ob * 256 + tid] = Pn[x16][y16];
            Lt_out[ob * 256 + tid] = Lt[x16][y16];
            if (tid < DX) {
                mu_pred_out[ob * DX + tid] = mu[1 - mup][tid];
                mu_t_out[ob * DX + tid]    = mut[tid];
            }
            P[x16][y16] = Pn[x16][y16];
        }
        if (tid == 0) {
            float md = wmax[0];
            #pragma unroll
            for (int w = 1; w < NT / 32; ++w) md = fmaxf(md, wmax[w]);
            convFlag = (md < CONV_EPS && t >= lastChange && t < TT - 1) ? 1 : 0;
        }
        mup = 1 - mup;
        __syncthreads();
        if (convFlag) { tconv = t + 1; break; }
    }

    // ================ Phase B: frozen-gain fast path ================
    if (tconv < TT) {
        // Fm = I - KC ; Mm = A * Fm ; frozen tiles
        Fm[x16][y16] = ((x16 == y16) ? 1.f : 0.f) - KC[x16][y16];
        LpTile[tid] = Pn[x16][y16];
        LtTile[tid] = Lt[x16][y16];
        __syncthreads();
        {
            float s = 0.f;
            #pragma unroll
            for (int z = 0; z < DX; ++z) s += As[x16][z] * Fm[z][y16];
            Mm[x16][y16] = s;
        }
        __syncthreads();

        const int wid  = tid >> 5;
        const int lane = tid & 31;

        // recurrence warp's register state
        float Frow[DX], Mrow[DX], muv = 0.f;
        if (wid == 0 && lane < DX) {
            #pragma unroll
            for (int j = 0; j < DX; ++j) { Frow[j] = Fm[lane][j]; Mrow[j] = Mm[lane][j]; }
            muv = mu[mup][lane];
        }
        __syncthreads();

        const float4* LpT4 = (const float4*)LpTile;
        const float4* LtT4 = (const float4*)LtTile;

        for (int t0 = tconv; t0 < TT; t0 += CH) {
            const int L = min(CH, TT - t0);

            // ---- stage a, u, mask chunk (coalesced float4) ----
            {
                const float4* a4 = (const float4*)(a_g + ((size_t)b * TT + t0) * DA);
                for (int i = tid; i < L * (DA / 4); i += NT)
                    ((float4*)abuf)[i] = a4[i];
                const float4* u4 = (const float4*)(u_g + ((size_t)b * TT + t0) * DU);
                for (int i = tid; i < L * (DU / 4); i += NT)
                    ((float4*)ubuf)[i] = u4[i];
                if (tid < L) mbuf[tid] = mask_g[(size_t)b * TT + t0 + tid];
            }
            __syncthreads();

            // ---- g_t = K*(m_t * a_t) ----
            for (int e = tid; e < L * DX; e += NT) {
                int s = e >> 4, x = e & 15;
                const float* ar = abuf + s * DA;
                float g = 0.f;
                #pragma unroll
                for (int aa = 0; aa < DA; ++aa) g += Kk[x][aa] * ar[aa];
                gbuf[s][x] = mbuf[s] * g;
            }
            __syncthreads();

            // ---- h_t = A*g_t + B*u_t (u=0 at final step) ----
            for (int e = tid; e < L * DX; e += NT) {
                int s = e >> 4, x = e & 15;
                float h = 0.f;
                #pragma unroll
                for (int z = 0; z < DX; ++z) h += As[x][z] * gbuf[s][z];
                if (t0 + s != TT - 1) {
                    const float* ur = ubuf + s * DU;
                    #pragma unroll
                    for (int uu = 0; uu < DU; ++uu) h += Bs[x][uu] * ur[uu];
                }
                hbuf[s][x] = h;
            }
            __syncthreads();

            if (wid == 0) {
                // ---- serial mu recurrence: registers + shuffles only ----
                for (int s = 0; s < L; ++s) {
                    float g = 0.f, h = 0.f;
                    if (lane < DX) { g = gbuf[s][lane]; h = hbuf[s][lane]; }
                    float mt0 = g, mt1 = 0.f, mn0 = h, mn1 = 0.f;
                    #pragma unroll
                    for (int j = 0; j < DX; j += 2) {
                        float mj0 = __shfl_sync(0xffffffffu, muv, j);
                        float mj1 = __shfl_sync(0xffffffffu, muv, j + 1);
                        mt0 = fmaf(Frow[j],     mj0, mt0);
                        mt1 = fmaf(Frow[j + 1], mj1, mt1);
                        mn0 = fmaf(Mrow[j],     mj0, mn0);
                        mn1 = fmaf(Mrow[j + 1], mj1, mn1);
                    }
                    float mt = mt0 + mt1;
                    float mn = mn0 + mn1;
                    if (lane < DX) {
                        size_t ob = (size_t)(t0 + s) * NB + b;
                        mu_t_out[ob * DX + lane]    = mt;
                        mu_pred_out[ob * DX + lane] = mn;
                    }
                    muv = mn;
                }
            } else {
                // ---- frozen Lambda fill: 7 warps, STG.128 ----
                const int ft    = tid - 32;              // 0..223
                const int total = L * 128;               // float4s: L steps x 2 arrays x 64
                for (int idx = ft; idx < total; idx += (NT - 32)) {
                    int s = idx >> 7, r = idx & 127;
                    float4 v = (r & 64) ? LtT4[r & 63] : LpT4[r & 63];
                    float* base = ((r & 64) ? Lt_out : Lp_out)
                                  + ((size_t)(t0 + s) * NB + b) * 256;
                    ((float4*)base)[r & 63] = v;
                }
            }
            __syncthreads();
        }
    }
}

extern "C" void kernel_launch(void* const* d_in, const int* in_sizes, int n_in,
                              void* d_out, int out_size)
{
    (void)in_sizes; (void)n_in; (void)out_size;
    ldm_forward_kernel<<<NB, NT>>>(
        (const float*)d_in[0],   // a
        (const float*)d_in[1],   // u
        (const float*)d_in[2],   // mask
        (const float*)d_in[3],   // A
        (const float*)d_in[4],   // B
        (const float*)d_in[5],   // C
        (const float*)d_in[6],   // mu_0
        (const float*)d_in[7],   // Lambda_0
        (const float*)d_in[8],   // W_log_diag
        (const float*)d_in[9],   // R_log_diag
        (float*)d_out);
}

// round 3
// speedup vs baseline: 2.2964x; 1.2310x over previous
#include <cuda_runtime.h>
#include <cuda_bf16.h>
#include <math.h>

#define TT 1024   // time steps
#define NB 256    // sequences
#define DX 16
#define DU 16
#define DA 32
#define NT 256    // threads per block
#define CH 32     // phase-B chunk length (multiple of 4)
#define SLABS 8   // fill-kernel T partitions
#define CONV_EPS 1e-7f

// scratch (allocation-free): frozen tiles + convergence step per sequence
__device__ __align__(16) float g_LpF[NB * 256];
__device__ __align__(16) float g_LtF[NB * 256];
__device__ int g_tconv[NB];

// ---- shared-memory pool offsets (floats) ----
// persistent
#define OFF_AS   0      // 16x17
#define OFF_BS   272    // 16x17
#define OFF_KK   544    // 16x33
#define OFF_MU   1072   // 2x16
// phase A overlay
#define OFF_CS   1104   // 32x17
#define OFF_P    1648   // 16x17
#define OFF_PCT  1920   // 16x33
#define OFF_KC   2448   // 16x17
#define OFF_LT   2720   // 16x17
#define OFF_AL   2992   // 16x17
#define OFF_PN   3264   // 16x17
#define OFF_SINV 3536   // 32x33
// phase B overlay (same region)
#define OFF_FM   1104   // 16x17
#define OFF_MM   1376
#define OFF_M2   1648
#define OFF_M3   1920
#define OFF_M4   2192
#define OFF_AB   2464   // CH x 32  (16B aligned: 2464*4 % 16 == 0)
#define OFF_UB   3488   // CH x 16
#define OFF_GB   4000   // CH x 17
#define OFF_HB   4544   // CH x 17
#define OFF_S1   5088   // 8 x 17
#define OFF_S2   5224
#define OFF_HH   5360
#define OFF_CHK  5496   // 9 x 17
#define OFF_PBF  5649   // CH x 17
#define OFF_MB   6193   // CH
#define POOLSZ   6240

__global__ __launch_bounds__(NT, 2)
void ldm_main(const float* __restrict__ a_g,
              const float* __restrict__ u_g,
              const float* __restrict__ mask_g,
              const float* __restrict__ A_g,
              const float* __restrict__ B_g,
              const float* __restrict__ C_g,
              const float* __restrict__ mu0_g,
              const float* __restrict__ Lam0_g,
              const float* __restrict__ Wl_g,
              const float* __restrict__ Rl_g,
              float* __restrict__ out)
{
    const int b   = blockIdx.x;
    const int tid = threadIdx.x;

    float* mu_pred_out = out;
    float* mu_t_out    = out + (size_t)TT * NB * DX;
    float* Lp_out      = out + (size_t)2 * TT * NB * DX;
    float* Lt_out      = Lp_out + (size_t)TT * NB * 256;

    __shared__ __align__(16) float pool[POOLSZ];
    __shared__ float Wd[DX], Rd[DA], sa[DA], su[DU], rr[DA], mut[DX];
    __shared__ float colk[2][DA], rowk[2][DA];
    __shared__ float wmax8[NT / 32];
    __shared__ float smv;
    __shared__ int   lastChange, convFlag;

    float* Asp  = pool + OFF_AS;
    float* Bsp  = pool + OFF_BS;
    float* KKp  = pool + OFF_KK;
    float* mu_  = pool + OFF_MU;
    float* Csp  = pool + OFF_CS;
    float* Pp   = pool + OFF_P;
    float* PCTp = pool + OFF_PCT;
    float* KCp  = pool + OFF_KC;
    float* LTp  = pool + OFF_LT;
    float* ALp  = pool + OFF_AL;
    float* PNp  = pool + OFF_PN;
    float* SIp  = pool + OFF_SINV;

    // ---------------- init ----------------
    for (int i = tid; i < DA * DX; i += NT) Csp[(i / DX) * 17 + (i % DX)] = C_g[i];
    for (int i = tid; i < DX * DX; i += NT) {
        Asp[(i / DX) * 17 + (i % DX)] = A_g[i];
        Pp [(i / DX) * 17 + (i % DX)] = Lam0_g[i];
    }
    for (int i = tid; i < DX * DU; i += NT) Bsp[(i / DU) * 17 + (i % DU)] = B_g[i];
    if (tid < DX) { Wd[tid] = expf(Wl_g[tid]); mu_[tid] = mu0_g[tid]; }
    if (tid < DA) Rd[tid] = expf(Rl_g[tid]);
    if (tid == 0) { lastChange = 0; convFlag = 0; }
    __syncthreads();

    {
        int lc = 0;
        for (int t = tid + 1; t < TT; t += NT)
            if (mask_g[(size_t)b * TT + t] != mask_g[(size_t)b * TT + t - 1]) lc = t;
        atomicMax(&lastChange, lc);
    }
    __syncthreads();

    const int x16  = tid >> 4,  y16  = tid & 15;
    const int wrow = tid >> 5,  jcol = tid & 31;

    int mup = 0, tconv = TT;

    // ================ Phase A ================
    for (int t = 0; t < TT; ++t) {
        if (tid < DA) sa[tid] = a_g[((size_t)b * TT + t) * DA + tid];
        if (tid < DU) su[tid] = (t == TT - 1) ? 0.f : u_g[((size_t)b * TT + t) * DU + tid];
        if (tid == 0) smv = mask_g[(size_t)b * TT + t];
        __syncthreads();
        const float m = smv;

        // PCt + residual
        #pragma unroll
        for (int q = 0; q < 2; ++q) {
            int e = tid + q * NT, x = e >> 5, aa = e & 31;
            float s = 0.f;
            #pragma unroll
            for (int y = 0; y < DX; ++y) s += Pp[x * 17 + y] * Csp[aa * 17 + y];
            PCTp[x * 33 + aa] = s;
        }
        if (tid < DA) {
            float s = 0.f;
            #pragma unroll
            for (int y = 0; y < DX; ++y) s += Csp[tid * 17 + y] * mu_[mup * 16 + y];
            rr[tid] = m * sa[tid] - s;
        }
        __syncthreads();

        // S directly into registers: thread owns (rows wrow+8q, col jcol)
        float pctj[DX];
        #pragma unroll
        for (int x = 0; x < DX; ++x) pctj[x] = PCTp[x * 33 + jcol];
        float Sreg[4];
        #pragma unroll
        for (int q = 0; q < 4; ++q) {
            int i = wrow + 8 * q;
            float s = (i == jcol) ? Rd[i] : 0.f;
            #pragma unroll
            for (int x = 0; x < DX; ++x) s += Csp[i * 17 + x] * pctj[x];
            Sreg[q] = s;
        }

        // register-resident Gauss-Jordan, 1 barrier per pivot
        #pragma unroll 1
        for (int k = 0; k < DA; ++k) {
            int par = k & 1;
            if (jcol == k) {
                #pragma unroll
                for (int q = 0; q < 4; ++q) colk[par][wrow + 8 * q] = Sreg[q];
            }
            if (wrow == (k & 7)) rowk[par][jcol] = Sreg[k >> 3];
            __syncthreads();
            float d   = __frcp_rn(rowk[par][k]);
            float rjj = (jcol == k) ? d : rowk[par][jcol] * d;
            #pragma unroll
            for (int q = 0; q < 4; ++q) {
                int i = wrow + 8 * q;
                float ci = colk[par][i];
                if (i == k) {
                    Sreg[q] = rjj;
                } else {
                    float base = (jcol == k) ? 0.f : Sreg[q];
                    Sreg[q] = fmaf(-ci, rjj, base);
                }
            }
        }
        #pragma unroll
        for (int q = 0; q < 4; ++q) SIp[(wrow + 8 * q) * 33 + jcol] = Sreg[q];
        __syncthreads();

        // K = m * PCt * Sinv
        #pragma unroll
        for (int q = 0; q < 2; ++q) {
            int e = tid + q * NT, x = e >> 5, aa = e & 31;
            float s = 0.f;
            #pragma unroll
            for (int jj = 0; jj < DA; ++jj) s += PCTp[x * 33 + jj] * SIp[jj * 33 + aa];
            KKp[x * 33 + aa] = m * s;
        }
        __syncthreads();

        // KC ; mu_t
        {
            float s = 0.f;
            #pragma unroll
            for (int aa = 0; aa < DA; ++aa) s += KKp[x16 * 33 + aa] * Csp[aa * 17 + y16];
            KCp[x16 * 17 + y16] = s;
        }
        if (tid < DX) {
            float s = mu_[mup * 16 + tid];
            #pragma unroll
            for (int aa = 0; aa < DA; ++aa) s += KKp[tid * 33 + aa] * rr[aa];
            mut[tid] = s;
        }
        __syncthreads();

        // Lam_t ; mu_pred'
        {
            float s = Pp[x16 * 17 + y16];
            #pragma unroll
            for (int z = 0; z < DX; ++z) s -= KCp[x16 * 17 + z] * Pp[z * 17 + y16];
            LTp[x16 * 17 + y16] = s;
        }
        if (tid < DX) {
            float s = 0.f;
            #pragma unroll
            for (int y = 0; y < DX; ++y) s += Asp[tid * 17 + y] * mut[y];
            #pragma unroll
            for (int uu = 0; uu < DU; ++uu) s += Bsp[tid * 17 + uu] * su[uu];
            mu_[(1 - mup) * 16 + tid] = s;
        }
        __syncthreads();

        // AL = A * Lam_t
        {
            float s = 0.f;
            #pragma unroll
            for (int z = 0; z < DX; ++z) s += Asp[x16 * 17 + z] * LTp[z * 17 + y16];
            ALp[x16 * 17 + y16] = s;
        }
        __syncthreads();

        // Pn = AL * A^T + W ; conv diff
        float mydiff;
        {
            float s = (x16 == y16) ? Wd[x16] : 0.f;
            #pragma unroll
            for (int z = 0; z < DX; ++z) s += ALp[x16 * 17 + z] * Asp[y16 * 17 + z];
            PNp[x16 * 17 + y16] = s;
            mydiff = fabsf(s - Pp[x16 * 17 + y16]);
        }
        #pragma unroll
        for (int o = 16; o; o >>= 1)
            mydiff = fmaxf(mydiff, __shfl_xor_sync(0xffffffffu, mydiff, o));
        if ((tid & 31) == 0) wmax8[tid >> 5] = mydiff;
        __syncthreads();

        {
            size_t ob = (size_t)t * NB + b;
            Lp_out[ob * 256 + tid] = PNp[x16 * 17 + y16];
            Lt_out[ob * 256 + tid] = LTp[x16 * 17 + y16];
            if (tid < DX) {
                mu_pred_out[ob * DX + tid] = mu_[(1 - mup) * 16 + tid];
                mu_t_out[ob * DX + tid]    = mut[tid];
            }
            Pp[x16 * 17 + y16] = PNp[x16 * 17 + y16];
        }
        if (tid == 0) {
            float md = wmax8[0];
            #pragma unroll
            for (int w = 1; w < NT / 32; ++w) md = fmaxf(md, wmax8[w]);
            convFlag = (md < CONV_EPS && t >= lastChange &&
                        (t + 1) < TT && (((t + 1) & 3) == 0)) ? 1 : 0;
        }
        mup = 1 - mup;
        __syncthreads();
        if (convFlag) { tconv = t + 1; break; }
    }

    if (tid == 0) g_tconv[b] = tconv;
    if (tconv >= TT) return;

    // frozen tiles -> scratch (fill kernel consumes them)
    g_LpF[b * 256 + tid] = PNp[x16 * 17 + y16];
    g_LtF[b * 256 + tid] = LTp[x16 * 17 + y16];

    // ================ Phase B setup: F, M, M^2, M^3, M^4 ================
    float* FMp = pool + OFF_FM;
    float* MMp = pool + OFF_MM;
    float* M2p = pool + OFF_M2;
    float* M3p = pool + OFF_M3;
    float* M4p = pool + OFF_M4;
    float* GBp = pool + OFF_GB;
    float* HBp = pool + OFF_HB;
    float* S1p = pool + OFF_S1;
    float* S2p = pool + OFF_S2;
    float* HHp = pool + OFF_HH;
    float* CHKp = pool + OFF_CHK;
    float* PBFp = pool + OFF_PBF;
    float* MBp  = pool + OFF_MB;

    float kcv = KCp[x16 * 17 + y16];
    __syncthreads();                     // everyone captured before overlay reuse
    FMp[x16 * 17 + y16] = ((x16 == y16) ? 1.f : 0.f) - kcv;
    __syncthreads();
    {
        float s = 0.f;
        #pragma unroll
        for (int z = 0; z < DX; ++z) s += Asp[x16 * 17 + z] * FMp[z * 17 + y16];
        MMp[x16 * 17 + y16] = s;
    }
    __syncthreads();
    {
        float s = 0.f;
        #pragma unroll
        for (int z = 0; z < DX; ++z) s += MMp[x16 * 17 + z] * MMp[z * 17 + y16];
        M2p[x16 * 17 + y16] = s;
    }
    __syncthreads();
    {
        float s3 = 0.f, s4 = 0.f;
        #pragma unroll
        for (int z = 0; z < DX; ++z) {
            s3 += M2p[x16 * 17 + z] * MMp[z * 17 + y16];
            s4 += M2p[x16 * 17 + z] * M2p[z * 17 + y16];
        }
        M3p[x16 * 17 + y16] = s3;
        M4p[x16 * 17 + y16] = s4;
    }
    __syncthreads();

    const int wid = tid >> 5, lane = tid & 31;
    float M4row[DX], muv = 0.f;
    if (wid == 0) {
        if (lane < DX) {
            #pragma unroll
            for (int j = 0; j < DX; ++j) M4row[j] = M4p[lane * 17 + j];
            muv = mu_[mup * 16 + lane];
        } else {
            #pragma unroll
            for (int j = 0; j < DX; ++j) M4row[j] = 0.f;
        }
    }

    // ================ Phase B chunks ================
    for (int t0 = tconv; t0 < TT; t0 += CH) {
        const int L   = min(CH, TT - t0);
        const int NGl = L >> 2;

        // stage a,u,mask
        {
            const float4* a4 = (const float4*)(a_g + ((size_t)b * TT + t0) * DA);
            for (int i2 = tid; i2 < L * 8; i2 += NT) ((float4*)(pool + OFF_AB))[i2] = a4[i2];
            const float4* u4 = (const float4*)(u_g + ((size_t)b * TT + t0) * DU);
            for (int i2 = tid; i2 < L * 4; i2 += NT) ((float4*)(pool + OFF_UB))[i2] = u4[i2];
            if (tid < L) MBp[tid] = mask_g[(size_t)b * TT + t0 + tid];
        }
        __syncthreads();

        // g_t = K*(m*a)
        for (int e = tid; e < L * DX; e += NT) {
            int s = e >> 4, x = e & 15;
            const float* ar = pool + OFF_AB + s * DA;
            float g = 0.f;
            #pragma unroll
            for (int aa = 0; aa < DA; ++aa) g += KKp[x * 33 + aa] * ar[aa];
            GBp[s * 17 + x] = MBp[s] * g;
        }
        __syncthreads();

        // h_t = A*g_t + B*u_t
        for (int e = tid; e < L * DX; e += NT) {
            int s = e >> 4, x = e & 15;
            float h = 0.f;
            #pragma unroll
            for (int z = 0; z < DX; ++z) h += Asp[x * 17 + z] * GBp[s * 17 + z];
            if (t0 + s != TT - 1) {
                const float* ur = pool + OFF_UB + s * DU;
                #pragma unroll
                for (int uu = 0; uu < DU; ++uu) h += Bsp[x * 17 + uu] * ur[uu];
            }
            HBp[s * 17 + x] = h;
        }
        __syncthreads();

        // group partials: s1 = M h0 + h1 ; s2 = M2 h0 + M h1 + h2 ;
        //                 hh = M3 h0 + M2 h1 + M h2 + h3
        for (int e = tid; e < NGl * DX; e += NT) {
            int q = e >> 4, x = e & 15;
            const float* h0 = HBp + (4 * q) * 17;
            float s1 = h0[17 + x], s2 = h0[34 + x], hh = h0[51 + x];
            #pragma unroll
            for (int j = 0; j < DX; ++j) {
                float h0j = h0[j], h1j = h0[17 + j], h2j = h0[34 + j];
                float mj  = MMp[x * 17 + j];
                float m2j = M2p[x * 17 + j];
                s1 = fmaf(mj,  h0j, s1);
                s2 = fmaf(m2j, h0j, fmaf(mj, h1j, s2));
                hh = fmaf(M3p[x * 17 + j], h0j, fmaf(m2j, h1j, fmaf(mj, h2j, hh)));
            }
            S1p[q * 17 + x] = s1;
            S2p[q * 17 + x] = s2;
            HHp[q * 17 + x] = hh;
        }
        __syncthreads();

        // serial stride-4 chain (warp 0): mu_chk[q+1] = M4 mu_chk[q] + hh_q
        if (wid == 0) {
            #pragma unroll 1
            for (int q = 0; q < NGl; ++q) {
                float nm = (lane < DX) ? HHp[q * 17 + lane] : 0.f;
                if (lane < DX) CHKp[q * 17 + lane] = muv;
                float a0 = nm, a1 = 0.f;
                #pragma unroll
                for (int j = 0; j < DX; j += 2) {
                    float m0 = __shfl_sync(0xffffffffu, muv, j);
                    float m1 = __shfl_sync(0xffffffffu, muv, j + 1);
                    a0 = fmaf(M4row[j],     m0, a0);
                    a1 = fmaf(M4row[j + 1], m1, a1);
                }
                muv = a0 + a1;
            }
            if (lane < DX) CHKp[NGl * 17 + lane] = muv;
        }
        __syncthreads();

        // pass1: reconstruct mu_pred(t) for all t in chunk
        for (int e = tid; e < L * DX; e += NT) {
            int s = e >> 4, x = e & 15, q = s >> 2, r = s & 3;
            float p;
            if (r == 0) {
                p = CHKp[q * 17 + x];
            } else {
                const float* Mr = (r == 1) ? MMp : (r == 2) ? M2p : M3p;
                p = (r == 1) ? HBp[(4 * q) * 17 + x]
                  : (r == 2) ? S1p[q * 17 + x] : S2p[q * 17 + x];
                #pragma unroll
                for (int j = 0; j < DX; ++j) p = fmaf(Mr[x * 17 + j], CHKp[q * 17 + j], p);
            }
            PBFp[s * 17 + x] = p;
        }
        __syncthreads();

        // pass2: mu_t = F*mu_pred + g ; outputs
        for (int e = tid; e < L * DX; e += NT) {
            int s = e >> 4, x = e & 15;
            int t = t0 + s;
            float mt = GBp[s * 17 + x];
            #pragma unroll
            for (int j = 0; j < DX; ++j) mt = fmaf(FMp[x * 17 + j], PBFp[s * 17 + j], mt);
            float mpn = (s + 1 < L) ? PBFp[(s + 1) * 17 + x] : CHKp[NGl * 17 + x];
            size_t ob = (size_t)t * NB + b;
            mu_t_out[ob * DX + x]    = mt;
            mu_pred_out[ob * DX + x] = mpn;
        }
        __syncthreads();
    }
}

// ---------------- frozen-Lambda fill at DRAM roofline ----------------
__global__ __launch_bounds__(NT)
void ldm_fill(float* __restrict__ out)
{
    const int b = blockIdx.x, slab = blockIdx.y, tid = threadIdx.x;
    float* Lp_out = out + (size_t)2 * TT * NB * DX;
    float* Lt_out = Lp_out + (size_t)TT * NB * 256;

    const int tb0 = slab * (TT / SLABS);
    const int tb1 = tb0 + (TT / SLABS);
    const int tc  = g_tconv[b];
    const int ts  = tc > tb0 ? tc : tb0;
    if (ts >= tb1) return;

    const int r   = tid & 127;           // which float4 of the 2KB tile pair
    const int rr2 = r & 63;
    const float4 val = (r < 64) ? ((const float4*)g_LpF)[b * 64 + rr2]
                                : ((const float4*)g_LtF)[b * 64 + rr2];
    float4* dst = (float4*)((r < 64) ? Lp_out : Lt_out);

    const int total = (tb1 - ts) * 128;
    for (int idx = tid; idx < total; idx += NT) {
        int t = ts + (idx >> 7);         // idx&127 == r stays fixed
        dst[((size_t)t * NB + b) * 64 + rr2] = val;
    }
}

extern "C" void kernel_launch(void* const* d_in, const int* in_sizes, int n_in,
                              void* d_out, int out_size)
{
    (void)in_sizes; (void)n_in; (void)out_size;
    ldm_main<<<NB, NT>>>(
        (const float*)d_in[0], (const float*)d_in[1], (const float*)d_in[2],
        (const float*)d_in[3], (const float*)d_in[4], (const float*)d_in[5],
        (const float*)d_in[6], (const float*)d_in[7], (const float*)d_in[8],
        (const float*)d_in[9], (float*)d_out);
    ldm_fill<<<dim3(NB, SLABS), NT>>>((float*)d_out);
}

// round 4
// speedup vs baseline: 3.9540x; 1.7218x over previous
#include <cuda_runtime.h>
#include <cuda_bf16.h>
#include <math.h>

#define TT 1024
#define NB 256
#define DX 16
#define DU 16
#define DA 32
#define NT 256
#define CH 32
#define SLABS 8
#define CONV_EPS 1e-5f

__device__ __align__(16) float g_LpF[NB * 256];
__device__ __align__(16) float g_LtF[NB * 256];
__device__ int g_tconv[NB];

// ---- shared pool offsets (floats) ----
// persistent
#define OFF_AS   0      // A [16][17]
#define OFF_BS   272    // B [16][17]
#define OFF_KK   544    // K [16][33]
#define OFF_MU   1072   // mu double buffer [2][16]
// phase A region
#define OFF_CS   1104   // C [32][17]
#define OFF_CT2  1648   // C^T R^-1 [16][33]
#define OFF_U    2176   // C^T R^-1 C [16][17]
#define OFF_LT   2448   // Lambda_t [16][17]
#define OFF_PA   2720   // Lambda_pred buf A [16][17]
#define OFF_PB   2992   // Lambda_pred buf B [16][17]
#define OFF_AL   3264   // A*Lambda_t [16][17]
// phase B overlay (>= 1104, written only after freeze)
#define OFF_FM   1104
#define OFF_MM   1376
#define OFF_M2   1648
#define OFF_M3   1920
#define OFF_M4   2192
#define OFF_AB   2464   // CH x 32
#define OFF_UB   3488   // CH x 16
#define OFF_GB   4000   // CH x 17
#define OFF_HB   4544   // CH x 17
#define OFF_S1   5088
#define OFF_S2   5224
#define OFF_HH   5360
#define OFF_CHK  5496
#define OFF_PBF  5649
#define OFF_MB   6193
#define POOLSZ   6240

// in-warp unrolled 16x16 Gauss-Jordan inverse (lane j owns column j&15)
__device__ __forceinline__ void inv16_warp(float Sc[DX], int lane)
{
    const unsigned FULL = 0xffffffffu;
    #pragma unroll
    for (int k = 0; k < DX; ++k) {
        float piv = __shfl_sync(FULL, Sc[k], k);
        float d   = __frcp_rn(piv);
        float rjj = (lane == k) ? d : Sc[k] * d;
        #pragma unroll
        for (int i = 0; i < DX; ++i) {
            if (i == k) continue;
            float cki  = __shfl_sync(FULL, Sc[i], k);
            float base = (lane == k) ? 0.f : Sc[i];
            Sc[i] = fmaf(-cki, rjj, base);
        }
        Sc[k] = rjj;
    }
}

__global__ __launch_bounds__(NT, 2)
void ldm_main(const float* __restrict__ a_g,
              const float* __restrict__ u_g,
              const float* __restrict__ mask_g,
              const float* __restrict__ A_g,
              const float* __restrict__ B_g,
              const float* __restrict__ C_g,
              const float* __restrict__ mu0_g,
              const float* __restrict__ Lam0_g,
              const float* __restrict__ Wl_g,
              const float* __restrict__ Rl_g,
              float* __restrict__ out)
{
    const int b   = blockIdx.x;
    const int tid = threadIdx.x;

    float* mu_pred_out = out;
    float* mu_t_out    = out + (size_t)TT * NB * DX;
    float* Lp_out      = out + (size_t)2 * TT * NB * DX;
    float* Lt_out      = Lp_out + (size_t)TT * NB * 256;

    __shared__ __align__(16) float pool[POOLSZ];
    __shared__ float Wd[DX], Rd[DA], sa[DA], su[DU], cr[DX], rr_raw[DA], mut[DX];
    __shared__ float wmax8[NT / 32];
    __shared__ float smv;
    __shared__ int   lastChange, convFlag;

    float* Asp  = pool + OFF_AS;
    float* Bsp  = pool + OFF_BS;
    float* KKp  = pool + OFF_KK;
    float* mu_  = pool + OFF_MU;
    float* Csp  = pool + OFF_CS;
    float* Ct2p = pool + OFF_CT2;
    float* Up   = pool + OFF_U;
    float* LTp  = pool + OFF_LT;
    float* ALp  = pool + OFF_AL;

    // ---------------- init ----------------
    for (int i = tid; i < DA * DX; i += NT) Csp[(i / DX) * 17 + (i % DX)] = C_g[i];
    for (int i = tid; i < DX * DX; i += NT) {
        Asp[(i / DX) * 17 + (i % DX)] = A_g[i];
        (pool + OFF_PA)[(i / DX) * 17 + (i % DX)] = Lam0_g[i];
    }
    for (int i = tid; i < DX * DU; i += NT) Bsp[(i / DU) * 17 + (i % DU)] = B_g[i];
    if (tid < DX) { Wd[tid] = expf(Wl_g[tid]); mu_[tid] = mu0_g[tid]; }
    if (tid < DA) Rd[tid] = expf(Rl_g[tid]);
    if (tid == 0) { lastChange = 0; convFlag = 0; }
    __syncthreads();

    // Ct2 = C^T R^-1 ; mask-change scan
    for (int i = tid; i < DX * DA; i += NT) {
        int x = i >> 5, aa = i & 31;
        Ct2p[x * 33 + aa] = Csp[aa * 17 + x] / Rd[aa];
    }
    {
        int lc = 0;
        for (int t = tid + 1; t < TT; t += NT)
            if (mask_g[(size_t)b * TT + t] != mask_g[(size_t)b * TT + t - 1]) lc = t;
        atomicMax(&lastChange, lc);
    }
    __syncthreads();

    const int x16 = tid >> 4, y16 = tid & 15;
    const int lane = tid & 31, wid = tid >> 5;
    const int lj   = lane & 15;          // column owned inside warp 0

    // U = Ct2 * C
    {
        float s = 0.f;
        #pragma unroll
        for (int aa = 0; aa < DA; ++aa) s += Ct2p[x16 * 33 + aa] * Csp[aa * 17 + y16];
        Up[x16 * 17 + y16] = s;
    }
    // stage t=0 inputs
    if (tid < DA) sa[tid] = a_g[(size_t)b * TT * DA + tid];
    if (tid >= 64 && tid < 64 + DU) su[tid - 64] = u_g[(size_t)b * TT * DU + (tid - 64)];
    if (tid == 96) smv = mask_g[(size_t)b * TT];
    if (tid >= 128 && tid < 128 + DA) {
        int aa = tid - 128;
        float s = 0.f;
        #pragma unroll
        for (int y = 0; y < DX; ++y) s += Csp[aa * 17 + y] * mu_[y];
        rr_raw[aa] = s;
    }
    __syncthreads();

    // warp-0 persistent registers
    float Jp[DX], Ucol[DX];
    if (wid == 0) {
        #pragma unroll
        for (int i = 0; i < DX; ++i) {
            Ucol[i] = Up[i * 17 + lj];
            Jp[i]   = (pool + OFF_PA)[i * 17 + lj];  // Lambda_0
        }
        inv16_warp(Jp, lj);                          // J_pred = Lambda_0^-1
    }

    int mup = 0, tconv = TT;
    float* Pcur  = pool + OFF_PA;
    float* Pnext = pool + OFF_PB;
    float mfreeze = 1.f;

    // ================ Phase A (information form) ================
    #pragma unroll 1
    for (int t = 0; t < TT; ++t) {
        const float m = smv;
        const bool doUpd = (m != 0.0f);

        if (doUpd) {
            if (wid == 0) {
                float Sc[DX];
                #pragma unroll
                for (int i = 0; i < DX; ++i) Sc[i] = Jp[i] + Ucol[i];
                inv16_warp(Sc, lj);                  // Lambda_t
                if (lane < DX) {
                    #pragma unroll
                    for (int i = 0; i < DX; ++i) LTp[i * 17 + lj] = Sc[i];
                }
            }
            // cr = Ct2 * (m*a - C mu_pred)   (warp 2, overlapped with inverse)
            if (tid >= 64 && tid < 64 + DX) {
                int x = tid - 64;
                float s = 0.f;
                #pragma unroll
                for (int aa = 0; aa < DA; ++aa)
                    s += Ct2p[x * 33 + aa] * (m * sa[aa] - rr_raw[aa]);
                cr[x] = s;
            }
        } else {
            LTp[x16 * 17 + y16] = Pcur[x16 * 17 + y16];   // Lambda_t = Lambda_pred
        }
        __syncthreads();   // B1: Lambda_t ready

        // AL = A * Lambda_t ; mu_t = mu_pred + m * Lambda_t * cr
        {
            float s = 0.f;
            #pragma unroll
            for (int z = 0; z < DX; ++z) s += Asp[x16 * 17 + z] * LTp[z * 17 + y16];
            ALp[x16 * 17 + y16] = s;
        }
        if (tid < DX) {
            float s = mu_[mup * 16 + tid];
            if (doUpd) {
                float acc = 0.f;
                #pragma unroll
                for (int j = 0; j < DX; ++j) acc += LTp[tid * 17 + j] * cr[j];
                s = fmaf(m, acc, s);
            }
            mut[tid] = s;
        }
        __syncthreads();   // B2

        // Pn = AL * A^T + W ; diff ; mu_pred' = A mu_t + B u_t
        float mydiff;
        {
            float s = (x16 == y16) ? Wd[x16] : 0.f;
            #pragma unroll
            for (int z = 0; z < DX; ++z) s += ALp[x16 * 17 + z] * Asp[y16 * 17 + z];
            Pnext[x16 * 17 + y16] = s;
            mydiff = fabsf(s - Pcur[x16 * 17 + y16]);
        }
        #pragma unroll
        for (int o = 16; o; o >>= 1)
            mydiff = fmaxf(mydiff, __shfl_xor_sync(0xffffffffu, mydiff, o));
        if (lane == 0) wmax8[wid] = mydiff;
        if (tid < DX) {
            float s = 0.f;
            #pragma unroll
            for (int y = 0; y < DX; ++y) s += Asp[tid * 17 + y] * mut[y];
            #pragma unroll
            for (int uu = 0; uu < DU; ++uu) s += Bsp[tid * 17 + uu] * su[uu];
            mu_[(1 - mup) * 16 + tid] = s;
        }
        __syncthreads();   // B3: Pn, mu', wmax ready

        // ---- stage 5: warp 0 inverts Pn -> J_pred' ; warps 1-7 do I/O ----
        if (wid == 0) {
            #pragma unroll
            for (int i = 0; i < DX; ++i) Jp[i] = Pnext[i * 17 + lj];
            inv16_warp(Jp, lj);
        } else {
            size_t ob = (size_t)t * NB + b;
            for (int i = tid - 32; i < 256; i += NT - 32) {
                int xi = i >> 4, yi = i & 15;
                Lp_out[ob * 256 + i] = Pnext[xi * 17 + yi];
                Lt_out[ob * 256 + i] = LTp[xi * 17 + yi];
            }
            if (tid >= 32 && tid < 32 + DX) mu_t_out[ob * DX + tid - 32] = mut[tid - 32];
            if (tid >= 48 && tid < 48 + DX)
                mu_pred_out[ob * DX + tid - 48] = mu_[(1 - mup) * 16 + tid - 48];
            if (t + 1 < TT) {
                const size_t base = (size_t)b * TT + t + 1;
                if (tid >= 64 && tid < 64 + DA) sa[tid - 64] = a_g[base * DA + tid - 64];
                if (tid >= 96 && tid < 96 + DU)
                    su[tid - 96] = (t + 1 == TT - 1) ? 0.f : u_g[base * DU + tid - 96];
                if (tid == 112) smv = mask_g[base];
                if (tid >= 128 && tid < 128 + DA) {
                    int aa = tid - 128;
                    float s = 0.f;
                    #pragma unroll
                    for (int y = 0; y < DX; ++y)
                        s += Csp[aa * 17 + y] * mu_[(1 - mup) * 16 + y];
                    rr_raw[aa] = s;
                }
            }
            if (tid == 127) {
                float md = wmax8[0];
                #pragma unroll
                for (int w = 1; w < NT / 32; ++w) md = fmaxf(md, wmax8[w]);
                convFlag = (md < CONV_EPS && t >= lastChange &&
                            (t + 1) < TT && (((t + 1) & 3) == 0)) ? 1 : 0;
            }
        }
        __syncthreads();   // B4

        mup = 1 - mup;
        { float* tp = Pcur; Pcur = Pnext; Pnext = tp; }
        if (convFlag) { tconv = t + 1; mfreeze = m; break; }
    }

    if (tid == 0) g_tconv[b] = tconv;
    if (tconv >= TT) return;

    // ---- freeze: save tiles, K = mfreeze * Lambda_t * Ct2 ----
    g_LpF[b * 256 + tid] = Pcur[x16 * 17 + y16];
    g_LtF[b * 256 + tid] = LTp[x16 * 17 + y16];
    #pragma unroll
    for (int q = 0; q < 2; ++q) {
        int e = tid + q * NT, x = e >> 5, aa = e & 31;
        float s = 0.f;
        #pragma unroll
        for (int y = 0; y < DX; ++y) s += LTp[x * 17 + y] * Ct2p[y * 33 + aa];
        KKp[x * 33 + aa] = mfreeze * s;
    }
    __syncthreads();

    // F = I - K*C  (compute in regs before overlay clobbers Csp)
    float fmv;
    {
        float s = (x16 == y16) ? 1.f : 0.f;
        #pragma unroll
        for (int aa = 0; aa < DA; ++aa) s -= KKp[x16 * 33 + aa] * Csp[aa * 17 + y16];
        fmv = s;
    }
    __syncthreads();

    float* FMp = pool + OFF_FM;
    float* MMp = pool + OFF_MM;
    float* M2p = pool + OFF_M2;
    float* M3p = pool + OFF_M3;
    float* M4p = pool + OFF_M4;
    float* GBp = pool + OFF_GB;
    float* HBp = pool + OFF_HB;
    float* S1p = pool + OFF_S1;
    float* S2p = pool + OFF_S2;
    float* HHp = pool + OFF_HH;
    float* CHKp = pool + OFF_CHK;
    float* PBFp = pool + OFF_PBF;
    float* MBp  = pool + OFF_MB;

    FMp[x16 * 17 + y16] = fmv;
    __syncthreads();
    {
        float s = 0.f;
        #pragma unroll
        for (int z = 0; z < DX; ++z) s += Asp[x16 * 17 + z] * FMp[z * 17 + y16];
        MMp[x16 * 17 + y16] = s;
    }
    __syncthreads();
    {
        float s = 0.f;
        #pragma unroll
        for (int z = 0; z < DX; ++z) s += MMp[x16 * 17 + z] * MMp[z * 17 + y16];
        M2p[x16 * 17 + y16] = s;
    }
    __syncthreads();
    {
        float s3 = 0.f, s4 = 0.f;
        #pragma unroll
        for (int z = 0; z < DX; ++z) {
            s3 += M2p[x16 * 17 + z] * MMp[z * 17 + y16];
            s4 += M2p[x16 * 17 + z] * M2p[z * 17 + y16];
        }
        M3p[x16 * 17 + y16] = s3;
        M4p[x16 * 17 + y16] = s4;
    }
    __syncthreads();

    float M4row[DX], muv = 0.f;
    if (wid == 0) {
        if (lane < DX) {
            #pragma unroll
            for (int j = 0; j < DX; ++j) M4row[j] = M4p[lane * 17 + j];
            muv = mu_[mup * 16 + lane];
        } else {
            #pragma unroll
            for (int j = 0; j < DX; ++j) M4row[j] = 0.f;
        }
    }

    // ================ Phase B ================
    for (int t0 = tconv; t0 < TT; t0 += CH) {
        const int L   = min(CH, TT - t0);
        const int NGl = L >> 2;

        {
            const float4* a4 = (const float4*)(a_g + ((size_t)b * TT + t0) * DA);
            for (int i2 = tid; i2 < L * 8; i2 += NT) ((float4*)(pool + OFF_AB))[i2] = a4[i2];
            const float4* u4 = (const float4*)(u_g + ((size_t)b * TT + t0) * DU);
            for (int i2 = tid; i2 < L * 4; i2 += NT) ((float4*)(pool + OFF_UB))[i2] = u4[i2];
            if (tid < L) MBp[tid] = mask_g[(size_t)b * TT + t0 + tid];
        }
        __syncthreads();

        for (int e = tid; e < L * DX; e += NT) {
            int s = e >> 4, x = e & 15;
            const float* ar = pool + OFF_AB + s * DA;
            float g = 0.f;
            #pragma unroll
            for (int aa = 0; aa < DA; ++aa) g += KKp[x * 33 + aa] * ar[aa];
            GBp[s * 17 + x] = MBp[s] * g;
        }
        __syncthreads();

        for (int e = tid; e < L * DX; e += NT) {
            int s = e >> 4, x = e & 15;
            float h = 0.f;
            #pragma unroll
            for (int z = 0; z < DX; ++z) h += Asp[x * 17 + z] * GBp[s * 17 + z];
            if (t0 + s != TT - 1) {
                const float* ur = pool + OFF_UB + s * DU;
                #pragma unroll
                for (int uu = 0; uu < DU; ++uu) h += Bsp[x * 17 + uu] * ur[uu];
            }
            HBp[s * 17 + x] = h;
        }
        __syncthreads();

        for (int e = tid; e < NGl * DX; e += NT) {
            int q = e >> 4, x = e & 15;
            const float* h0 = HBp + (4 * q) * 17;
            float s1 = h0[17 + x], s2 = h0[34 + x], hh = h0[51 + x];
            #pragma unroll
            for (int j = 0; j < DX; ++j) {
                float h0j = h0[j], h1j = h0[17 + j], h2j = h0[34 + j];
                float mj  = MMp[x * 17 + j];
                float m2j = M2p[x * 17 + j];
                s1 = fmaf(mj,  h0j, s1);
                s2 = fmaf(m2j, h0j, fmaf(mj, h1j, s2));
                hh = fmaf(M3p[x * 17 + j], h0j, fmaf(m2j, h1j, fmaf(mj, h2j, hh)));
            }
            S1p[q * 17 + x] = s1;
            S2p[q * 17 + x] = s2;
            HHp[q * 17 + x] = hh;
        }
        __syncthreads();

        if (wid == 0) {
            #pragma unroll 1
            for (int q = 0; q < NGl; ++q) {
                float nm = (lane < DX) ? HHp[q * 17 + lane] : 0.f;
                if (lane < DX) CHKp[q * 17 + lane] = muv;
                float a0 = nm, a1 = 0.f;
                #pragma unroll
                for (int j = 0; j < DX; j += 2) {
                    float m0 = __shfl_sync(0xffffffffu, muv, j);
                    float m1 = __shfl_sync(0xffffffffu, muv, j + 1);
                    a0 = fmaf(M4row[j],     m0, a0);
                    a1 = fmaf(M4row[j + 1], m1, a1);
                }
                muv = a0 + a1;
            }
            if (lane < DX) CHKp[NGl * 17 + lane] = muv;
        }
        __syncthreads();

        for (int e = tid; e < L * DX; e += NT) {
            int s = e >> 4, x = e & 15, q = s >> 2, r = s & 3;
            float p;
            if (r == 0) {
                p = CHKp[q * 17 + x];
            } else {
                const float* Mr = (r == 1) ? MMp : (r == 2) ? M2p : M3p;
                p = (r == 1) ? HBp[(4 * q) * 17 + x]
                  : (r == 2) ? S1p[q * 17 + x] : S2p[q * 17 + x];
                #pragma unroll
                for (int j = 0; j < DX; ++j) p = fmaf(Mr[x * 17 + j], CHKp[q * 17 + j], p);
            }
            PBFp[s * 17 + x] = p;
        }
        __syncthreads();

        for (int e = tid; e < L * DX; e += NT) {
            int s = e >> 4, x = e & 15;
            int t = t0 + s;
            float mt = GBp[s * 17 + x];
            #pragma unroll
            for (int j = 0; j < DX; ++j) mt = fmaf(FMp[x * 17 + j], PBFp[s * 17 + j], mt);
            float mpn = (s + 1 < L) ? PBFp[(s + 1) * 17 + x] : CHKp[NGl * 17 + x];
            size_t ob = (size_t)t * NB + b;
            mu_t_out[ob * DX + x]    = mt;
            mu_pred_out[ob * DX + x] = mpn;
        }
        __syncthreads();
    }
}

__global__ __launch_bounds__(NT)
void ldm_fill(float* __restrict__ out)
{
    const int b = blockIdx.x, slab = blockIdx.y, tid = threadIdx.x;
    float* Lp_out = out + (size_t)2 * TT * NB * DX;
    float* Lt_out = Lp_out + (size_t)TT * NB * 256;

    const int tb0 = slab * (TT / SLABS);
    const int tb1 = tb0 + (TT / SLABS);
    const int tc  = g_tconv[b];
    const int ts  = tc > tb0 ? tc : tb0;
    if (ts >= tb1) return;

    const int r   = tid & 127;
    const int rr2 = r & 63;
    const float4 val = (r < 64) ? ((const float4*)g_LpF)[b * 64 + rr2]
                                : ((const float4*)g_LtF)[b * 64 + rr2];
    float4* dst = (float4*)((r < 64) ? Lp_out : Lt_out);

    const int total = (tb1 - ts) * 128;
    for (int idx = tid; idx < total; idx += NT) {
        int t = ts + (idx >> 7);
        dst[((size_t)t * NB + b) * 64 + rr2] = val;
    }
}

extern "C" void kernel_launch(void* const* d_in, const int* in_sizes, int n_in,
                              void* d_out, int out_size)
{
    (void)in_sizes; (void)n_in; (void)out_size;
    ldm_main<<<NB, NT>>>(
        (const float*)d_in[0], (const float*)d_in[1], (const float*)d_in[2],
        (const float*)d_in[3], (const float*)d_in[4], (const float*)d_in[5],
        (const float*)d_in[6], (const float*)d_in[7], (const float*)d_in[8],
        (const float*)d_in[9], (float*)d_out);
    ldm_fill<<<dim3(NB, SLABS), NT>>>((float*)d_out);
}

// round 5
// speedup vs baseline: 4.5846x; 1.1595x over previous
#include <cuda_runtime.h>
#include <cuda_bf16.h>
#include <math.h>

#define TT 1024
#define NB 256
#define DX 16
#define DU 16
#define DA 32
#define NT 256
#define CH 64
#define SLABS 8
#define CONV_EPS 1e-5f

__device__ __align__(16) float g_LpF[NB * 256];
__device__ __align__(16) float g_LtF[NB * 256];
__device__ __align__(16) float g_K[NB * 512];
__device__ float g_muc[NB * 16];
__device__ int g_tconv[NB];

// in-warp unrolled 16x16 Gauss-Jordan inverse (lane j owns column j&15).
// Safe without pivoting for SPD input.
__device__ __forceinline__ void inv16_warp(float Sc[DX], int lane)
{
    const unsigned FULL = 0xffffffffu;
    #pragma unroll
    for (int k = 0; k < DX; ++k) {
        float piv = __shfl_sync(FULL, Sc[k], k);
        float d   = __frcp_rn(piv);
        float rjj = (lane == k) ? d : Sc[k] * d;
        #pragma unroll
        for (int i = 0; i < DX; ++i) {
            if (i == k) continue;
            float cki  = __shfl_sync(FULL, Sc[i], k);
            float base = (lane == k) ? 0.f : Sc[i];
            Sc[i] = fmaf(-cki, rjj, base);
        }
        Sc[k] = rjj;
    }
}

// ==================== Phase A: exact Kalman steps until freeze ====================
__global__ __launch_bounds__(NT, 2)
void ldm_phaseA(const float* __restrict__ a_g,
                const float* __restrict__ u_g,
                const float* __restrict__ mask_g,
                const float* __restrict__ A_g,
                const float* __restrict__ B_g,
                const float* __restrict__ C_g,
                const float* __restrict__ mu0_g,
                const float* __restrict__ Lam0_g,
                const float* __restrict__ Wl_g,
                const float* __restrict__ Rl_g,
                float* __restrict__ out)
{
    const int b   = blockIdx.x;
    const int tid = threadIdx.x;

    float* mu_pred_out = out;
    float* mu_t_out    = out + (size_t)TT * NB * DX;
    float* Lp_out      = out + (size_t)2 * TT * NB * DX;
    float* Lt_out      = Lp_out + (size_t)TT * NB * 256;

    __shared__ float Cs[DA * 17];     // C
    __shared__ float Ct2[DX * 33];    // C^T R^-1
    __shared__ float As[DX * 17];
    __shared__ float Bs[DX * 17];
    __shared__ float Us[DX * 17];     // C^T R^-1 C
    __shared__ float Pbuf[2][DX * 17];
    __shared__ float LTs[DX * 17];
    __shared__ float ALs[DX * 17];
    __shared__ float TIs[DX * 17];    // (P + U^-1)^-1
    __shared__ float Vs[DX * 17];     // T^-1 P
    __shared__ float Wd[DX], Rd[DA];
    __shared__ float sa[2][DA], su[2][DU], smv2[2];
    __shared__ float rr[DA], cr[DX];
    __shared__ float muS[2][DX], mut[DX];
    __shared__ float wmax8[NT / 32];
    __shared__ int   lastChange, convFlag;

    // ---------------- init ----------------
    for (int i = tid; i < DA * DX; i += NT) Cs[(i / DX) * 17 + (i % DX)] = C_g[i];
    for (int i = tid; i < DX * DX; i += NT) {
        As[(i / DX) * 17 + (i % DX)]      = A_g[i];
        Pbuf[0][(i / DX) * 17 + (i % DX)] = Lam0_g[i];
    }
    for (int i = tid; i < DX * DU; i += NT) Bs[(i / DU) * 17 + (i % DU)] = B_g[i];
    if (tid < DX) { Wd[tid] = expf(Wl_g[tid]); muS[0][tid] = mu0_g[tid]; }
    if (tid < DA) Rd[tid] = expf(Rl_g[tid]);
    if (tid == 0) { lastChange = 0; convFlag = 0; }
    __syncthreads();

    for (int i = tid; i < DX * DA; i += NT) {
        int x = i >> 5, aa = i & 31;
        Ct2[x * 33 + aa] = Cs[aa * 17 + x] / Rd[aa];
    }
    {
        int lc = 0;
        for (int t = tid + 1; t < TT; t += NT)
            if (mask_g[(size_t)b * TT + t] != mask_g[(size_t)b * TT + t - 1]) lc = t;
        atomicMax(&lastChange, lc);
    }
    __syncthreads();

    const int x16 = tid >> 4, y16 = tid & 15;
    const int lane = tid & 31, wid = tid >> 5;
    const int lj   = lane & 15;

    // U = Ct2 * C ; stage t=0
    {
        float s = 0.f;
        #pragma unroll
        for (int aa = 0; aa < DA; ++aa) s += Ct2[x16 * 33 + aa] * Cs[aa * 17 + y16];
        Us[x16 * 17 + y16] = s;
    }
    if (tid < DA) sa[0][tid] = a_g[(size_t)b * TT * DA + tid];
    if (tid >= 64 && tid < 64 + DU) su[0][tid - 64] = u_g[(size_t)b * TT * DU + (tid - 64)];
    if (tid == 96) smv2[0] = mask_g[(size_t)b * TT];
    if (tid >= 128 && tid < 128 + DA) {
        int aa = tid - 128;
        float s = 0.f;
        #pragma unroll
        for (int y = 0; y < DX; ++y) s += Cs[aa * 17 + y] * muS[0][y];
        rr[aa] = s;
    }
    __syncthreads();

    // warp-0 persistent registers: Uinv columns
    float Uic[DX];
    if (wid == 0) {
        #pragma unroll
        for (int i = 0; i < DX; ++i) Uic[i] = Us[i * 17 + lj];
        inv16_warp(Uic, lj);           // Uic = U^-1 column lj
    }

    float* Pcur  = Pbuf[0];
    float* Pnext = Pbuf[1];
    int tconv = TT;
    float mfreeze = 1.f;

    // ================ main loop ================
    #pragma unroll 1
    for (int t = 0; t < TT; ++t) {
        const int p = t & 1;
        const float m = smv2[p];
        const bool doUpd = (m != 0.0f);

        // ---- R1: warp0 inverts T = P + U^-1 ; warp2 residual ; warps6-7 prefetch
        if (doUpd && wid == 0) {
            float Tc[DX];
            #pragma unroll
            for (int i = 0; i < DX; ++i) Tc[i] = Pcur[i * 17 + lj] + Uic[i];
            inv16_warp(Tc, lj);
            if (lane < DX) {
                #pragma unroll
                for (int i = 0; i < DX; ++i) TIs[i * 17 + lj] = Tc[i];
            }
        }
        if (doUpd && tid >= 64 && tid < 64 + DX) {
            int x = tid - 64;
            float s = 0.f;
            #pragma unroll
            for (int aa = 0; aa < DA; ++aa)
                s += Ct2[x * 33 + aa] * (m * sa[p][aa] - rr[aa]);
            cr[x] = s;
        }
        if (t + 1 < TT) {
            const size_t base = (size_t)b * TT + t + 1;
            if (tid >= 192 && tid < 192 + DA) sa[1 - p][tid - 192] = a_g[base * DA + tid - 192];
            if (tid >= 224 && tid < 224 + DU)
                su[1 - p][tid - 224] = (t + 1 == TT - 1) ? 0.f : u_g[base * DU + tid - 224];
            if (tid == 240) smv2[1 - p] = mask_g[base];
        }
        __syncthreads();   // B1

        // ---- R2: V = T^-1 * P
        if (doUpd) {
            float s = 0.f;
            #pragma unroll
            for (int z = 0; z < DX; ++z) s += TIs[x16 * 17 + z] * Pcur[z * 17 + y16];
            Vs[x16 * 17 + y16] = s;
        }
        __syncthreads();   // B2

        // ---- R3: Lambda_t = P - P*V  (or P if masked out)
        {
            float s = Pcur[x16 * 17 + y16];
            if (doUpd) {
                #pragma unroll
                for (int z = 0; z < DX; ++z) s -= Pcur[x16 * 17 + z] * Vs[z * 17 + y16];
            }
            LTs[x16 * 17 + y16] = s;
        }
        __syncthreads();   // B3

        // ---- R4: AL = A*Lambda_t ; mu_t
        {
            float s = 0.f;
            #pragma unroll
            for (int z = 0; z < DX; ++z) s += As[x16 * 17 + z] * LTs[z * 17 + y16];
            ALs[x16 * 17 + y16] = s;
        }
        if (tid < DX) {
            float s = muS[p][tid];
            if (doUpd) {
                float acc = 0.f;
                #pragma unroll
                for (int j = 0; j < DX; ++j) acc += LTs[tid * 17 + j] * cr[j];
                s = fmaf(m, acc, s);
            }
            mut[tid] = s;
        }
        __syncthreads();   // B4

        // ---- R5: Pn = AL*A^T + W ; diff ; mu_pred'
        float mydiff;
        {
            float s = (x16 == y16) ? Wd[x16] : 0.f;
            #pragma unroll
            for (int z = 0; z < DX; ++z) s += ALs[x16 * 17 + z] * As[y16 * 17 + z];
            Pnext[x16 * 17 + y16] = s;
            mydiff = fabsf(s - Pcur[x16 * 17 + y16]);
        }
        #pragma unroll
        for (int o = 16; o; o >>= 1)
            mydiff = fmaxf(mydiff, __shfl_xor_sync(0xffffffffu, mydiff, o));
        if (lane == 0) wmax8[wid] = mydiff;
        if (tid < DX) {
            float s = 0.f;
            #pragma unroll
            for (int y = 0; y < DX; ++y) s += As[tid * 17 + y] * mut[y];
            #pragma unroll
            for (int uu = 0; uu < DU; ++uu) s += Bs[tid * 17 + uu] * su[p][uu];
            muS[1 - p][tid] = s;
        }
        __syncthreads();   // B5

        // ---- R6: outputs for step t ; rr for t+1 ; conv decision
        {
            size_t ob = (size_t)t * NB + b;
            Lp_out[ob * 256 + tid] = Pnext[x16 * 17 + y16];
            Lt_out[ob * 256 + tid] = LTs[x16 * 17 + y16];
            if (tid < DX) mu_t_out[ob * DX + tid] = mut[tid];
            else if (tid < 2 * DX) mu_pred_out[ob * DX + tid - DX] = muS[1 - p][tid - DX];
        }
        if (tid >= 128 && tid < 128 + DA) {
            int aa = tid - 128;
            float s = 0.f;
            #pragma unroll
            for (int y = 0; y < DX; ++y) s += Cs[aa * 17 + y] * muS[1 - p][y];
            rr[aa] = s;
        }
        if (tid == 255) {
            float md = wmax8[0];
            #pragma unroll
            for (int w = 1; w < NT / 32; ++w) md = fmaxf(md, wmax8[w]);
            convFlag = (md < CONV_EPS && t >= lastChange &&
                        (t + 1) < TT && (((t + 1) & 3) == 0)) ? 1 : 0;
        }
        __syncthreads();   // B6

        { float* tp = Pcur; Pcur = Pnext; Pnext = tp; }
        if (convFlag) { tconv = t + 1; mfreeze = m; break; }
    }

    if (tid == 0) g_tconv[b] = tconv;
    if (tconv >= TT) return;

    // ---- freeze bookkeeping for the tail kernel ----
    g_LpF[b * 256 + tid] = Pcur[x16 * 17 + y16];
    g_LtF[b * 256 + tid] = LTs[x16 * 17 + y16];
    #pragma unroll
    for (int q = 0; q < 2; ++q) {
        int e = tid + q * NT, x = e >> 5, aa = e & 31;
        float s = 0.f;
        #pragma unroll
        for (int y = 0; y < DX; ++y) s += LTs[x * 17 + y] * Ct2[y * 33 + aa];
        g_K[b * 512 + x * 32 + aa] = mfreeze * s;
    }
    if (tid < DX) g_muc[b * 16 + tid] = muS[tconv & 1][tid];
}

// ==================== tail: Lambda fill (y>=1) + mu Phase B (y==0) ====================
__global__ __launch_bounds__(NT)
void ldm_tail(const float* __restrict__ a_g,
              const float* __restrict__ u_g,
              const float* __restrict__ mask_g,
              const float* __restrict__ A_g,
              const float* __restrict__ B_g,
              const float* __restrict__ C_g,
              float* __restrict__ out)
{
    const int b = blockIdx.x, tid = threadIdx.x;
    float* mu_pred_out = out;
    float* mu_t_out    = out + (size_t)TT * NB * DX;
    float* Lp_out      = out + (size_t)2 * TT * NB * DX;
    float* Lt_out      = Lp_out + (size_t)TT * NB * 256;

    if (blockIdx.y > 0) {
        // ---------------- Lambda fill slab ----------------
        const int slab = blockIdx.y - 1;
        const int tb0 = slab * (TT / SLABS);
        const int tb1 = tb0 + (TT / SLABS);
        const int tc  = g_tconv[b];
        const int ts  = tc > tb0 ? tc : tb0;
        if (ts >= tb1) return;

        const int r   = tid & 127;
        const int rr2 = r & 63;
        const float4 val = (r < 64) ? ((const float4*)g_LpF)[b * 64 + rr2]
                                    : ((const float4*)g_LtF)[b * 64 + rr2];
        float4* dst = (float4*)((r < 64) ? Lp_out : Lt_out);
        const int total = (tb1 - ts) * 128;
        for (int idx = tid; idx < total; idx += NT) {
            int t = ts + (idx >> 7);
            dst[((size_t)t * NB + b) * 64 + rr2] = val;
        }
        return;
    }

    // ---------------- Phase B: frozen-gain mu recurrence ----------------
    const int tconv = g_tconv[b];
    if (tconv >= TT) return;

    __shared__ float As[DX * 17], Bs[DX * 17], Cs[DA * 17], Ks[DX * 33];
    __shared__ float FM[DX * 17], MM[DX * 17], M2s[DX * 17], M3s[DX * 17], M4s[DX * 17];
    __shared__ __align__(16) float AB[CH * DA];
    __shared__ __align__(16) float UB[CH * DU];
    __shared__ float GB[CH * 17], HB[CH * 17];
    __shared__ float S1[(CH / 4) * 17], S2[(CH / 4) * 17], HH[(CH / 4) * 17];
    __shared__ float CHK[(CH / 4 + 1) * 17];
    __shared__ float PBF[CH * 17];
    __shared__ float MB[CH];

    const int x16 = tid >> 4, y16 = tid & 15;
    const int lane = tid & 31, wid = tid >> 5;

    for (int i = tid; i < DA * DX; i += NT) Cs[(i / DX) * 17 + (i % DX)] = C_g[i];
    for (int i = tid; i < DX * DX; i += NT) As[(i / DX) * 17 + (i % DX)] = A_g[i];
    for (int i = tid; i < DX * DU; i += NT) Bs[(i / DU) * 17 + (i % DU)] = B_g[i];
    #pragma unroll
    for (int q = 0; q < 2; ++q) {
        int e = tid + q * NT;
        Ks[(e >> 5) * 33 + (e & 31)] = g_K[b * 512 + e];
    }
    __syncthreads();

    {
        float s = (x16 == y16) ? 1.f : 0.f;
        #pragma unroll
        for (int aa = 0; aa < DA; ++aa) s -= Ks[x16 * 33 + aa] * Cs[aa * 17 + y16];
        FM[x16 * 17 + y16] = s;
    }
    __syncthreads();
    {
        float s = 0.f;
        #pragma unroll
        for (int z = 0; z < DX; ++z) s += As[x16 * 17 + z] * FM[z * 17 + y16];
        MM[x16 * 17 + y16] = s;
    }
    __syncthreads();
    {
        float s = 0.f;
        #pragma unroll
        for (int z = 0; z < DX; ++z) s += MM[x16 * 17 + z] * MM[z * 17 + y16];
        M2s[x16 * 17 + y16] = s;
    }
    __syncthreads();
    {
        float s3 = 0.f, s4 = 0.f;
        #pragma unroll
        for (int z = 0; z < DX; ++z) {
            s3 += M2s[x16 * 17 + z] * MM[z * 17 + y16];
            s4 += M2s[x16 * 17 + z] * M2s[z * 17 + y16];
        }
        M3s[x16 * 17 + y16] = s3;
        M4s[x16 * 17 + y16] = s4;
    }
    __syncthreads();

    float M4row[DX], muv = 0.f;
    if (wid == 0) {
        if (lane < DX) {
            #pragma unroll
            for (int j = 0; j < DX; ++j) M4row[j] = M4s[lane * 17 + j];
            muv = g_muc[b * 16 + lane];
        } else {
            #pragma unroll
            for (int j = 0; j < DX; ++j) M4row[j] = 0.f;
        }
    }

    for (int t0 = tconv; t0 < TT; t0 += CH) {
        const int L   = min(CH, TT - t0);
        const int NGl = L >> 2;

        {
            const float4* a4 = (const float4*)(a_g + ((size_t)b * TT + t0) * DA);
            for (int i2 = tid; i2 < L * 8; i2 += NT) ((float4*)AB)[i2] = a4[i2];
            const float4* u4 = (const float4*)(u_g + ((size_t)b * TT + t0) * DU);
            for (int i2 = tid; i2 < L * 4; i2 += NT) ((float4*)UB)[i2] = u4[i2];
            if (tid < L) MB[tid] = mask_g[(size_t)b * TT + t0 + tid];
        }
        __syncthreads();

        for (int e = tid; e < L * DX; e += NT) {
            int s = e >> 4, x = e & 15;
            const float* ar = AB + s * DA;
            float g = 0.f;
            #pragma unroll
            for (int aa = 0; aa < DA; ++aa) g += Ks[x * 33 + aa] * ar[aa];
            GB[s * 17 + x] = MB[s] * g;
        }
        __syncthreads();

        for (int e = tid; e < L * DX; e += NT) {
            int s = e >> 4, x = e & 15;
            float h = 0.f;
            #pragma unroll
            for (int z = 0; z < DX; ++z) h += As[x * 17 + z] * GB[s * 17 + z];
            if (t0 + s != TT - 1) {
                const float* ur = UB + s * DU;
                #pragma unroll
                for (int uu = 0; uu < DU; ++uu) h += Bs[x * 17 + uu] * ur[uu];
            }
            HB[s * 17 + x] = h;
        }
        __syncthreads();

        for (int e = tid; e < NGl * DX; e += NT) {
            int q = e >> 4, x = e & 15;
            const float* h0 = HB + (4 * q) * 17;
            float s1 = h0[17 + x], s2 = h0[34 + x], hh = h0[51 + x];
            #pragma unroll
            for (int j = 0; j < DX; ++j) {
                float h0j = h0[j], h1j = h0[17 + j], h2j = h0[34 + j];
                float mj  = MM[x * 17 + j];
                float m2j = M2s[x * 17 + j];
                s1 = fmaf(mj,  h0j, s1);
                s2 = fmaf(m2j, h0j, fmaf(mj, h1j, s2));
                hh = fmaf(M3s[x * 17 + j], h0j, fmaf(m2j, h1j, fmaf(mj, h2j, hh)));
            }
            S1[q * 17 + x] = s1;
            S2[q * 17 + x] = s2;
            HH[q * 17 + x] = hh;
        }
        __syncthreads();

        if (wid == 0) {
            #pragma unroll 1
            for (int q = 0; q < NGl; ++q) {
                float nm = (lane < DX) ? HH[q * 17 + lane] : 0.f;
                if (lane < DX) CHK[q * 17 + lane] = muv;
                float a0 = nm, a1 = 0.f;
                #pragma unroll
                for (int j = 0; j < DX; j += 2) {
                    float m0 = __shfl_sync(0xffffffffu, muv, j);
                    float m1 = __shfl_sync(0xffffffffu, muv, j + 1);
                    a0 = fmaf(M4row[j],     m0, a0);
                    a1 = fmaf(M4row[j + 1], m1, a1);
                }
                muv = a0 + a1;
            }
            if (lane < DX) CHK[NGl * 17 + lane] = muv;
        }
        __syncthreads();

        for (int e = tid; e < L * DX; e += NT) {
            int s = e >> 4, x = e & 15, q = s >> 2, r = s & 3;
            float pv;
            if (r == 0) {
                pv = CHK[q * 17 + x];
            } else {
                const float* Mr = (r == 1) ? MM : (r == 2) ? M2s : M3s;
                pv = (r == 1) ? HB[(4 * q) * 17 + x]
                   : (r == 2) ? S1[q * 17 + x] : S2[q * 17 + x];
                #pragma unroll
                for (int j = 0; j < DX; ++j) pv = fmaf(Mr[x * 17 + j], CHK[q * 17 + j], pv);
            }
            PBF[s * 17 + x] = pv;
        }
        __syncthreads();

        for (int e = tid; e < L * DX; e += NT) {
            int s = e >> 4, x = e & 15;
            int t = t0 + s;
            float mt = GB[s * 17 + x];
            #pragma unroll
            for (int j = 0; j < DX; ++j) mt = fmaf(FM[x * 17 + j], PBF[s * 17 + j], mt);
            float mpn = (s + 1 < L) ? PBF[(s + 1) * 17 + x] : CHK[NGl * 17 + x];
            size_t ob = (size_t)t * NB + b;
            mu_t_out[ob * DX + x]    = mt;
            mu_pred_out[ob * DX + x] = mpn;
        }
        __syncthreads();
    }
}

extern "C" void kernel_launch(void* const* d_in, const int* in_sizes, int n_in,
                              void* d_out, int out_size)
{
    (void)in_sizes; (void)n_in; (void)out_size;
    ldm_phaseA<<<NB, NT>>>(
        (const float*)d_in[0], (const float*)d_in[1], (const float*)d_in[2],
        (const float*)d_in[3], (const float*)d_in[4], (const float*)d_in[5],
        (const float*)d_in[6], (const float*)d_in[7], (const float*)d_in[8],
        (const float*)d_in[9], (float*)d_out);
    ldm_tail<<<dim3(NB, SLABS + 1), NT>>>(
        (const float*)d_in[0], (const float*)d_in[1], (const float*)d_in[2],
        (const float*)d_in[3], (const float*)d_in[4], (const float*)d_in[5],
        (float*)d_out);
}